// round 17
// baseline (speedup 1.0000x reference)
#include <cuda_runtime.h>
#include <cuda_fp16.h>
#include <math.h>
#include <stdint.h>

// ===========================================================================
// img_attention via warp-level FP16 mma.sync m16n8k16 (compute_103-safe)
//   c_img = softmax(v . tanh(Wh g* + Ws s + Wc cov)) @ g*
//   g*    = X @ (W_g @ W_gs) + (b_g @ W_gs + b_gs)      [algebraic fold]
// R16: two-stream forked graph — side stream (conv X, WhT, WsT, s_t, sproj)
//      overlaps the main critical path (WgsT/W_g prep -> Wcomb -> gstar).
//      Kernels identical to R15.
// ===========================================================================

#define B_   128
#define N_   49
#define G_   4096
#define H_   1024
#define A_   1024
#define BN_  (B_ * N_)   // 6272

__device__ __half g_Xh[BN_ * G_];
__device__ __half g_Wgh[G_ * G_];
__device__ __half g_WgsTh[H_ * G_];
__device__ __half g_WcombTh[H_ * G_];
__device__ __half g_WhTh[A_ * H_];
__device__ __half g_WsTh[A_ * H_];
__device__ __half g_sth[B_ * H_];
__device__ __half g_gstarh[BN_ * H_];
__device__ __half g_parts[3 * BN_ * H_];
__device__ float  g_biascomb[H_];
__device__ float  g_sproj[B_ * A_];
__device__ float  g_scores[BN_];

// --- streams/events created once at program load (outside capture) --------
static cudaStream_t g_s1 = 0, g_s2 = 0;
static cudaEvent_t  g_evRoot = 0, g_evP = 0, g_evS = 0, g_evDone = 0;
namespace {
struct StreamInit {
    StreamInit() {
        cudaStreamCreateWithFlags(&g_s1, cudaStreamNonBlocking);
        cudaStreamCreateWithFlags(&g_s2, cudaStreamNonBlocking);
        cudaEventCreateWithFlags(&g_evRoot, cudaEventDisableTiming);
        cudaEventCreateWithFlags(&g_evP,    cudaEventDisableTiming);
        cudaEventCreateWithFlags(&g_evS,    cudaEventDisableTiming);
        cudaEventCreateWithFlags(&g_evDone, cudaEventDisableTiming);
    }
};
static StreamInit g_si;
}

// ---------------------------------------------------------------------------
__device__ __forceinline__ uint32_t smem_u32(const void* p) {
    uint32_t a;
    asm("{ .reg .u64 t; cvta.to.shared.u64 t, %1; cvt.u32.u64 %0, t; }"
        : "=r"(a) : "l"(p));
    return a;
}
__device__ __forceinline__ float tanh_approx(float x) {
    float y;
    asm("tanh.approx.f32 %0, %1;" : "=f"(y) : "f"(x));
    return y;
}
__device__ __forceinline__ void ldsm4(uint32_t* r, uint32_t addr) {
    asm volatile("ldmatrix.sync.aligned.m8n8.x4.shared.b16 {%0,%1,%2,%3}, [%4];"
                 : "=r"(r[0]), "=r"(r[1]), "=r"(r[2]), "=r"(r[3]) : "r"(addr));
}
__device__ __forceinline__ void mma_f16(float* d, const uint32_t* a,
                                        const uint32_t* b) {
    asm volatile(
        "mma.sync.aligned.m16n8k16.row.col.f32.f16.f16.f32 "
        "{%0,%1,%2,%3}, {%4,%5,%6,%7}, {%8,%9}, {%0,%1,%2,%3};"
        : "+f"(d[0]), "+f"(d[1]), "+f"(d[2]), "+f"(d[3])
        : "r"(a[0]), "r"(a[1]), "r"(a[2]), "r"(a[3]), "r"(b[0]), "r"(b[1]));
}
#define CPA(dst, src) \
    asm volatile("cp.async.cg.shared.global [%0], [%1], 16;" \
                 :: "r"(dst), "l"(src) : "memory")
#define CPCOMMIT() asm volatile("cp.async.commit_group;" ::: "memory")
#define CPWAIT1()  asm volatile("cp.async.wait_group 1;" ::: "memory")
#define CPWAIT0()  asm volatile("cp.async.wait_group 0;" ::: "memory")

// ---------------------------------------------------------------------------
// GEMM core (fp16). FM = A-fragments per warp (M-tile = FM*32).
// BK = 64 fp16 = 128B rows. 3-stage cp.async ring, frag double-buffer.
// ---------------------------------------------------------------------------
template <int FM>
struct GemmDims {
    static const int ABYTES = FM * 32 * 128;
    static const int STAGE  = ABYTES + 16384;
    static const int SMEM   = 3 * STAGE;
    static const int OCC    = (FM == 2) ? 3 : 2;
};

#define GEMM_PROLOG(FM)                                                       \
    extern __shared__ char smem[];                                            \
    const uint32_t sb = smem_u32(smem);                                       \
    const int tid = threadIdx.x;                                              \
    const int lane = tid & 31;                                                \
    const int wid = tid >> 5;                                                 \
    const int wr = wid >> 1;                                                  \
    const int wc = wid & 1;                                                   \
    const int srow = tid >> 3, sc4 = tid & 7;                                 \
    const uint32_t soff0 = (uint32_t)srow * 128 + ((sc4 ^ (srow & 7)) << 4);  \
    const int aRow = wr * (FM * 16) + ((lane >> 3) & 1) * 8 + (lane & 7);     \
    const int cbA = lane >> 4;                                                \
    const uint32_t aBase = (uint32_t)aRow * 128;                              \
    const int rmA = aRow & 7;                                                 \
    const int bRow = wc * 64 + (lane >> 4) * 8 + (lane & 7);                  \
    const int cbB = (lane >> 3) & 1;                                          \
    const uint32_t bBase = (uint32_t)bRow * 128;                              \
    const int rmB = bRow & 7;                                                 \
    float acc[FM][8][4];                                                      \
    _Pragma("unroll") for (int i = 0; i < FM; i++)                            \
        _Pragma("unroll") for (int j = 0; j < 8; j++)                         \
            _Pragma("unroll") for (int q = 0; q < 4; q++) acc[i][j][q] = 0.f;

template <int FM>
__device__ __forceinline__ void gemm_core(
    const __half* __restrict__ pA0, const __half* __restrict__ pB0,
    size_t strideJ, int nch, uint32_t sb, uint32_t soff0,
    uint32_t aBase, int rmA, int cbA,
    uint32_t bBase, int rmB, int cbB,
    float (&acc)[FM][8][4])
{
    const int ABYTES = GemmDims<FM>::ABYTES;
    const int STAGE  = GemmDims<FM>::STAGE;
    const int JA = FM * 2;

    auto issue = [&](uint32_t sbase, int k0) {
        #pragma unroll
        for (int j = 0; j < JA; j++)
            CPA(sbase + soff0 + j * 2048, pA0 + k0 + j * strideJ);
        #pragma unroll
        for (int j = 0; j < 8; j++)
            CPA(sbase + ABYTES + soff0 + j * 2048, pB0 + k0 + j * strideJ);
        CPCOMMIT();
    };

    uint32_t afr[2][FM][4], bfr[2][8][2];

    auto ldA = [&](uint32_t As, int kc, int buf) {
        #pragma unroll
        for (int fm = 0; fm < FM; fm++)
            ldsm4(afr[buf][fm],
                  As + fm * 2048 + aBase + ((((kc * 2) + cbA) ^ rmA) << 4));
    };
    auto ldB = [&](uint32_t Bs, int kc, int buf) {
        #pragma unroll
        for (int p = 0; p < 4; p++) {
            uint32_t t4[4];
            ldsm4(t4, Bs + p * 2048 + bBase + ((((kc * 2) + cbB) ^ rmB) << 4));
            bfr[buf][2*p][0]   = t4[0]; bfr[buf][2*p][1]   = t4[1];
            bfr[buf][2*p+1][0] = t4[2]; bfr[buf][2*p+1][1] = t4[3];
        }
    };

    issue(sb, 0);
    issue(sb + STAGE, 64);
    int cs = 0, is = 2;
    for (int c = 0; c < nch; c++) {
        if (c == nch - 1) { CPWAIT0(); } else { CPWAIT1(); }
        __syncthreads();
        if (c + 2 < nch) {
            issue(sb + is * STAGE, (c + 2) * 64);
            is = (is == 2) ? 0 : is + 1;
        }
        const uint32_t As = sb + cs * STAGE;
        const uint32_t Bs = As + ABYTES;
        ldA(As, 0, 0);
        ldB(Bs, 0, 0);
        #pragma unroll
        for (int kc = 0; kc < 4; kc++) {
            const int cur = kc & 1;
            if (kc < 3) {
                ldA(As, kc + 1, cur ^ 1);
                ldB(Bs, kc + 1, cur ^ 1);
            }
            #pragma unroll
            for (int fm = 0; fm < FM; fm++)
                #pragma unroll
                for (int fn = 0; fn < 8; fn++)
                    mma_f16(acc[fm][fn], afr[cur][fm], bfr[cur][fn]);
        }
        cs = (cs == 2) ? 0 : cs + 1;
    }
}

// ---------------------------------------------------------------------------
// Full-K GEMM with direct fp16 store (Wcomb): Ch = fp16(A @ Bt^T).
// ---------------------------------------------------------------------------
__global__ __launch_bounds__(128, 2)
void mma_gemm_h(const __half* __restrict__ A, const __half* __restrict__ Bt,
                __half* __restrict__ Ch, int Nn, int K)
{
    const int bm = blockIdx.y * 128;
    const int bn = blockIdx.x * 128;
    GEMM_PROLOG(4);
    const __half* pA0 = A  + (size_t)(bm + srow) * K + sc4 * 8;
    const __half* pB0 = Bt + (size_t)(bn + srow) * K + sc4 * 8;
    const size_t strideJ = (size_t)16 * K;
    gemm_core<4>(pA0, pB0, strideJ, K >> 6, sb, soff0,
                 aBase, rmA, cbA, bBase, rmB, cbB, acc);

    const int gid = lane >> 2, tig = lane & 3;
    #pragma unroll
    for (int fm = 0; fm < 4; fm++) {
        const int row = bm + wr * 64 + fm * 16 + gid;
        #pragma unroll
        for (int fn = 0; fn < 8; fn++) {
            const int col = bn + wc * 64 + fn * 8 + tig * 2;
            *(__half2*)(Ch + (size_t)row * Nn + col) =
                __floats2half2_rn(acc[fm][fn][0], acc[fm][fn][1]);
            *(__half2*)(Ch + (size_t)(row + 8) * Nn + col) =
                __floats2half2_rn(acc[fm][fn][2], acc[fm][fn][3]);
        }
    }
}

// ---------------------------------------------------------------------------
// Split-K partial GEMM (gstar): Cpart[z] = fp16(A @ Bt^T over K slice z).
// ---------------------------------------------------------------------------
__global__ __launch_bounds__(128, 2)
void mma_gemm_part(const __half* __restrict__ A, const __half* __restrict__ Bt,
                   __half* __restrict__ Cparts, size_t zstride,
                   int Nn, int K, int nchA)
{
    const int bm = blockIdx.y * 128;
    const int bn = blockIdx.x * 128;
    const int z  = blockIdx.z;
    const int kbase = z * nchA * 64;
    int nch = (K >> 6) - z * nchA;
    if (nch > nchA) nch = nchA;
    __half* C = Cparts + (size_t)z * zstride;

    GEMM_PROLOG(4);
    const __half* pA0 = A  + (size_t)(bm + srow) * K + kbase + sc4 * 8;
    const __half* pB0 = Bt + (size_t)(bn + srow) * K + kbase + sc4 * 8;
    const size_t strideJ = (size_t)16 * K;
    gemm_core<4>(pA0, pB0, strideJ, nch, sb, soff0,
                 aBase, rmA, cbA, bBase, rmB, cbB, acc);

    const int gid = lane >> 2, tig = lane & 3;
    #pragma unroll
    for (int fm = 0; fm < 4; fm++) {
        const int row = bm + wr * 64 + fm * 16 + gid;
        #pragma unroll
        for (int fn = 0; fn < 8; fn++) {
            const int col = bn + wc * 64 + fn * 8 + tig * 2;
            *(__half2*)(C + (size_t)row * Nn + col) =
                __floats2half2_rn(acc[fm][fn][0], acc[fm][fn][1]);
            *(__half2*)(C + (size_t)(row + 8) * Nn + col) =
                __floats2half2_rn(acc[fm][fn][2], acc[fm][fn][3]);
        }
    }
}

// ---------------------------------------------------------------------------
// Split-K GEMM for skinny M=128 (sproj): atomics into zeroed C.
// ---------------------------------------------------------------------------
__global__ __launch_bounds__(128, 2)
void mma_gemm_splitk(const __half* __restrict__ A, const __half* __restrict__ Bt,
                     float* __restrict__ C, int M, int Nn, int K, int klen)
{
    const int bm = blockIdx.y * 128;
    const int bn = blockIdx.x * 128;
    const int kbase = blockIdx.z * klen;
    GEMM_PROLOG(4);
    const __half* pA0 = A  + (size_t)(bm + srow) * K + kbase + sc4 * 8;
    const __half* pB0 = Bt + (size_t)(bn + srow) * K + kbase + sc4 * 8;
    const size_t strideJ = (size_t)16 * K;
    gemm_core<4>(pA0, pB0, strideJ, klen >> 6, sb, soff0,
                 aBase, rmA, cbA, bBase, rmB, cbB, acc);

    const int gid = lane >> 2, tig = lane & 3;
    #pragma unroll
    for (int fm = 0; fm < 4; fm++) {
        const int row = bm + wr * 64 + fm * 16 + gid;
        #pragma unroll
        for (int fn = 0; fn < 8; fn++) {
            const int col = bn + wc * 64 + fn * 8 + tig * 2;
            atomicAdd(C + (size_t)row * Nn + col,       acc[fm][fn][0]);
            atomicAdd(C + (size_t)row * Nn + col + 1,   acc[fm][fn][1]);
            atomicAdd(C + (size_t)(row+8) * Nn + col,   acc[fm][fn][2]);
            atomicAdd(C + (size_t)(row+8) * Nn + col+1, acc[fm][fn][3]);
        }
    }
}

// ---------------------------------------------------------------------------
// Fused e_pre GEMM + scores epilogue (FM=2 tiles, 3 CTAs/SM).
// ---------------------------------------------------------------------------
__global__ __launch_bounds__(128, 3)
void epre_scores_gemm(const __half* __restrict__ A, const __half* __restrict__ Bt,
                      const float* __restrict__ sproj,
                      const float* __restrict__ cov,
                      const float* __restrict__ Wc,
                      const float* __restrict__ v,
                      float* __restrict__ scores)
{
    const int bm = blockIdx.y * 64;
    const int bn = blockIdx.x * 128;
    GEMM_PROLOG(2);
    const __half* pA0 = A  + (size_t)(bm + srow) * H_ + sc4 * 8;
    const __half* pB0 = Bt + (size_t)(bn + srow) * H_ + sc4 * 8;
    const size_t strideJ = (size_t)16 * H_;
    gemm_core<2>(pA0, pB0, strideJ, H_ >> 6, sb, soff0,
                 aBase, rmA, cbA, bBase, rmB, cbB, acc);

    const int gid = lane >> 2, tig = lane & 3;
    float vv[16], wcv[16];
    #pragma unroll
    for (int fn = 0; fn < 8; fn++) {
        const int col = bn + wc * 64 + fn * 8 + tig * 2;
        vv[2*fn]   = v[col];      vv[2*fn+1]  = v[col + 1];
        wcv[2*fn]  = Wc[col];     wcv[2*fn+1] = Wc[col + 1];
    }
    #pragma unroll
    for (int fm = 0; fm < 2; fm++) {
        const int r0 = bm + wr * 32 + fm * 16 + gid;
        const int r1 = r0 + 8;
        const int b0i = r0 / N_, b1i = r1 / N_;
        const float c0 = cov[r0], c1 = cov[r1];
        const float* sp0 = sproj + (size_t)b0i * A_;
        const float* sp1 = sproj + (size_t)b1i * A_;
        float p0 = 0.f, p1 = 0.f;
        #pragma unroll
        for (int fn = 0; fn < 8; fn++) {
            const int col = bn + wc * 64 + fn * 8 + tig * 2;
            p0 += vv[2*fn]   * tanh_approx(acc[fm][fn][0] + sp0[col]     + c0 * wcv[2*fn]);
            p0 += vv[2*fn+1] * tanh_approx(acc[fm][fn][1] + sp0[col + 1] + c0 * wcv[2*fn+1]);
            p1 += vv[2*fn]   * tanh_approx(acc[fm][fn][2] + sp1[col]     + c1 * wcv[2*fn]);
            p1 += vv[2*fn+1] * tanh_approx(acc[fm][fn][3] + sp1[col + 1] + c1 * wcv[2*fn+1]);
        }
        p0 += __shfl_xor_sync(0xffffffffu, p0, 1);
        p0 += __shfl_xor_sync(0xffffffffu, p0, 2);
        p1 += __shfl_xor_sync(0xffffffffu, p1, 1);
        p1 += __shfl_xor_sync(0xffffffffu, p1, 2);
        if (tig == 0) {
            atomicAdd(scores + r0, p0);
            atomicAdd(scores + r1, p1);
        }
    }
}

// ---------------------------------------------------------------------------
// gstarh = fp16(p0+p1+p2 + biascomb[col] + b_gs[col])  (fp16 partials)
// ---------------------------------------------------------------------------
__global__ __launch_bounds__(256) void reduce3_bias_kernel(
    const __half* __restrict__ p0, const __half* __restrict__ p1,
    const __half* __restrict__ p2, const float* __restrict__ biascomb,
    const float* __restrict__ b_gs, __half* __restrict__ outh)
{
    const size_t i = ((size_t)blockIdx.x * 256 + threadIdx.x) * 4;
    const int col = (int)(i & (H_ - 1));
    const __half2* a2 = (const __half2*)(p0 + i);
    const __half2* b2 = (const __half2*)(p1 + i);
    const __half2* c2 = (const __half2*)(p2 + i);
    float2 a0 = __half22float2(a2[0]), a1 = __half22float2(a2[1]);
    float2 b0 = __half22float2(b2[0]), b1 = __half22float2(b2[1]);
    float2 c0 = __half22float2(c2[0]), c1 = __half22float2(c2[1]);
    float4 d = *(const float4*)(biascomb + col);
    float4 e = *(const float4*)(b_gs + col);
    *(__half2*)(outh + i) =
        __floats2half2_rn(a0.x + b0.x + c0.x + d.x + e.x,
                          a0.y + b0.y + c0.y + d.y + e.y);
    *(__half2*)(outh + i + 2) =
        __floats2half2_rn(a1.x + b1.x + c1.x + d.z + e.z,
                          a1.y + b1.y + c1.y + d.w + e.w);
}

// ---------------------------------------------------------------------------
// Prep kernels (split for stream overlap).
// main: WgsT transpose + conv W_g + bias_acc  (Wcomb/reduce3 prerequisites)
// side: conv X + WhT + WsT + conv s_t          (gstar-A / epre-B / sproj)
// ---------------------------------------------------------------------------
__device__ __forceinline__ void conv8(const float* __restrict__ in,
                                      __half* __restrict__ out, size_t i8) {
    float4 a = *(const float4*)(in + i8);
    float4 b = *(const float4*)(in + i8 + 4);
    __half2 h[4];
    h[0] = __floats2half2_rn(a.x, a.y);
    h[1] = __floats2half2_rn(a.z, a.w);
    h[2] = __floats2half2_rn(b.x, b.y);
    h[3] = __floats2half2_rn(b.z, b.w);
    *(uint4*)(out + i8) = *(const uint4*)h;
}

__device__ __forceinline__ void do_transpose32h(
    const float* __restrict__ in, __half* __restrict__ out,
    int R, int C, int tx, int ty)
{
    __shared__ float t[32][33];
    const int c0 = tx * 32, r0 = ty * 32;
    const int x = threadIdx.x & 31, y = (threadIdx.x >> 5);
    #pragma unroll
    for (int j = 0; j < 32; j += 8)
        t[y + j][x] = in[(size_t)(r0 + y + j) * C + c0 + x];
    __syncthreads();
    #pragma unroll
    for (int j = 0; j < 32; j += 8)
        out[(size_t)(c0 + y + j) * R + r0 + x] = __float2half_rn(t[x][y + j]);
}

#define PM_T1 4096                 // WgsT transpose
#define PM_CW (PM_T1 + 8192)       // conv W_g
#define PM_BA (PM_CW + 64)         // bias_acc
#define PM_END PM_BA

__global__ __launch_bounds__(256) void prep_main_kernel(
    const float* __restrict__ W_gs, __half* __restrict__ WgsTh,
    const float* __restrict__ W_g,  __half* __restrict__ Wgh,
    const float* __restrict__ b_g,  float* __restrict__ biascomb)
{
    const int bid = blockIdx.x;
    if (bid < PM_T1) {
        do_transpose32h(W_gs, WgsTh, G_, H_, bid & 31, bid >> 5);
    } else if (bid < PM_CW) {
        conv8(W_g, Wgh, ((size_t)(bid - PM_T1) * 256 + threadIdx.x) * 8);
    } else {
        const int b = bid - PM_CW;          // 0..63
        const int h = (b & 3) * 256 + threadIdx.x;
        const int k0 = (b >> 2) * 256;
        float acc = 0.f;
        #pragma unroll 4
        for (int k = k0; k < k0 + 256; k++)
            acc += b_g[k] * W_gs[(size_t)k * H_ + h];
        atomicAdd(&biascomb[h], acc);
    }
}

#define PS_CX 12544                // conv X
#define PS_TH (PS_CX + 1024)       // WhT
#define PS_TS (PS_TH + 1024)       // WsT
#define PS_CS (PS_TS + 64)         // conv s_t
#define PS_END PS_CS

__global__ __launch_bounds__(256) void prep_side_kernel(
    const float* __restrict__ X,    __half* __restrict__ Xh,
    const float* __restrict__ W_h,  __half* __restrict__ WhTh,
    const float* __restrict__ W_s,  __half* __restrict__ WsTh,
    const float* __restrict__ s_t,  __half* __restrict__ sth)
{
    const int bid = blockIdx.x;
    if (bid < PS_CX) {
        conv8(X, Xh, ((size_t)bid * 256 + threadIdx.x) * 8);
    } else if (bid < PS_TH) {
        const int b = bid - PS_CX;
        do_transpose32h(W_h, WhTh, H_, A_, b & 31, b >> 5);
    } else if (bid < PS_TS) {
        const int b = bid - PS_TH;
        do_transpose32h(W_s, WsTh, H_, A_, b & 31, b >> 5);
    } else {
        conv8(s_t, sth, ((size_t)(bid - PS_TS) * 256 + threadIdx.x) * 8);
    }
}

// softmax over N=49 + context c[b,h] = sum_n alpha[n] * gstarh[b,n,h]
__global__ __launch_bounds__(256) void context_kernel(
    const float* __restrict__ scores, const __half* __restrict__ gstarh,
    float* __restrict__ out)
{
    const int b = blockIdx.x;
    __shared__ float alpha[N_];
    const int tid = threadIdx.x;

    if (tid == 0) {
        float m = -1e30f;
        #pragma unroll
        for (int n = 0; n < N_; n++) m = fmaxf(m, scores[b * N_ + n]);
        float s = 0.f;
        #pragma unroll
        for (int n = 0; n < N_; n++) {
            float e = expf(scores[b * N_ + n] - m);
            alpha[n] = e;
            s += e;
        }
        float inv = 1.f / s;
        #pragma unroll
        for (int n = 0; n < N_; n++) alpha[n] *= inv;
    }
    __syncthreads();

    const __half* gb = gstarh + (size_t)b * N_ * H_;
    for (int h = tid; h < H_; h += 256) {
        float acc = 0.f;
        #pragma unroll
        for (int n = 0; n < N_; n++)
            acc += alpha[n] * __half2float(gb[(size_t)n * H_ + h]);
        out[(size_t)b * H_ + h] = acc;
    }
}

// ---------------------------------------------------------------------------
extern "C" void kernel_launch(void* const* d_in, const int* in_sizes, int n_in,
                              void* d_out, int out_size) {
    const float* X    = (const float*)d_in[0];
    const float* s_t  = (const float*)d_in[1];
    const float* cov  = (const float*)d_in[2];
    const float* W_g  = (const float*)d_in[3];
    const float* b_g  = (const float*)d_in[4];
    const float* W_gs = (const float*)d_in[5];
    const float* b_gs = (const float*)d_in[6];
    const float* W_h  = (const float*)d_in[7];
    const float* W_s  = (const float*)d_in[8];
    const float* W_c  = (const float*)d_in[9];
    const float* v    = (const float*)d_in[10];
    float* out = (float*)d_out;

    __half *Xh, *Wgh, *WgsTh, *WcombTh, *WhTh, *WsTh, *sth, *gstarh, *parts;
    float *biascomb, *sproj, *scores;
    cudaGetSymbolAddress((void**)&Xh,       g_Xh);
    cudaGetSymbolAddress((void**)&Wgh,      g_Wgh);
    cudaGetSymbolAddress((void**)&WgsTh,    g_WgsTh);
    cudaGetSymbolAddress((void**)&WcombTh,  g_WcombTh);
    cudaGetSymbolAddress((void**)&WhTh,     g_WhTh);
    cudaGetSymbolAddress((void**)&WsTh,     g_WsTh);
    cudaGetSymbolAddress((void**)&sth,      g_sth);
    cudaGetSymbolAddress((void**)&gstarh,   g_gstarh);
    cudaGetSymbolAddress((void**)&parts,    g_parts);
    cudaGetSymbolAddress((void**)&biascomb, g_biascomb);
    cudaGetSymbolAddress((void**)&sproj,    g_sproj);
    cudaGetSymbolAddress((void**)&scores,   g_scores);

    const int SM4 = GemmDims<4>::SMEM;   // 96KB
    const int SM2 = GemmDims<2>::SMEM;   // 72KB
    cudaFuncSetAttribute(mma_gemm_h,
                         cudaFuncAttributeMaxDynamicSharedMemorySize, SM4);
    cudaFuncSetAttribute(mma_gemm_part,
                         cudaFuncAttributeMaxDynamicSharedMemorySize, SM4);
    cudaFuncSetAttribute(mma_gemm_splitk,
                         cudaFuncAttributeMaxDynamicSharedMemorySize, SM4);
    cudaFuncSetAttribute(epre_scores_gemm,
                         cudaFuncAttributeMaxDynamicSharedMemorySize, SM2);

    // zero-fills on the capture-origin stream, then fork
    cudaMemsetAsync(biascomb, 0, H_ * sizeof(float));
    cudaMemsetAsync(scores,   0, BN_ * sizeof(float));
    cudaMemsetAsync(sproj,    0, (size_t)B_ * A_ * sizeof(float));
    cudaEventRecord(g_evRoot, 0);
    cudaStreamWaitEvent(g_s1, g_evRoot, 0);
    cudaStreamWaitEvent(g_s2, g_evRoot, 0);

    // --- side stream: conv X / WhT / WsT / s_t, then sproj GEMM
    prep_side_kernel<<<PS_END, 256, 0, g_s2>>>(X, Xh, W_h, WhTh, W_s, WsTh,
                                               s_t, sth);
    cudaEventRecord(g_evP, g_s2);   // Xh + WhTh ready marker
    mma_gemm_splitk<<<dim3(A_ / 128, 1, 8), 128, SM4, g_s2>>>(
        sth, WsTh, sproj, B_, A_, H_, H_ / 8);
    cudaEventRecord(g_evS, g_s2);   // sproj ready

    // --- main stream: prep_main -> Wcomb -> gstar -> reduce3 -> epre -> ctx
    prep_main_kernel<<<PM_END, 256, 0, g_s1>>>(W_gs, WgsTh, W_g, Wgh,
                                               b_g, biascomb);
    mma_gemm_h<<<dim3(G_ / 128, H_ / 128), 128, SM4, g_s1>>>(
        WgsTh, Wgh, WcombTh, G_, G_);

    cudaStreamWaitEvent(g_s1, g_evP, 0);            // need Xh
    mma_gemm_part<<<dim3(H_ / 128, BN_ / 128, 3), 128, SM4, g_s1>>>(
        Xh, WcombTh, parts, (size_t)BN_ * H_, H_, G_, 22);
    reduce3_bias_kernel<<<(BN_ * H_ / 4) / 256, 256, 0, g_s1>>>(
        parts, parts + (size_t)BN_ * H_, parts + 2 * (size_t)BN_ * H_,
        biascomb, b_gs, gstarh);

    cudaStreamWaitEvent(g_s1, g_evS, 0);            // need sproj
    epre_scores_gemm<<<dim3(A_ / 128, BN_ / 64), 128, SM2, g_s1>>>(
        gstarh, WhTh, sproj, cov, W_c, v, scores);
    context_kernel<<<B_, 256, 0, g_s1>>>(scores, gstarh, out);

    // join back to the origin stream
    cudaEventRecord(g_evDone, g_s1);
    cudaStreamWaitEvent(0, g_evDone, 0);
}